// round 5
// baseline (speedup 1.0000x reference)
#include <cuda_runtime.h>

// Problem constants
#define NN  32
#define CC  64
#define TT  256
#define VV  50
#define HH  8
#define HCC 8
#define KA  65            // augmented K (64 channels + bias row)
#define TCH 8             // t-chunks for scores kernel
#define TPC (TT / TCH)    // 32 t per scores block
#define TB  2             // t per block in fused output kernel
#define UP  56            // padded u/v extent (mult of 8)

// Scratch (static device memory — no allocations allowed)
__device__ float g_wf_t[HH][KA][CC];               // fused weights, k-major: [h][k][o]
__device__ float g_spart[TCH][NN][HH][VV][VV];     // partial scores
__device__ float g_attn[NN][HH][VV][VV];           // tanh(scores)*alpha + global_attn

// Packed fp32x2 FMA with scalar multiplier broadcast (Blackwell FFMA2)
__device__ __forceinline__ float2 ffma2s(float a, float2 b, float2 c) {
    float2 d;
    asm("{\n\t"
        ".reg .b64 ra, rb, rc;\n\t"
        "mov.b64 ra, {%2, %2};\n\t"
        "mov.b64 rb, {%3, %4};\n\t"
        "mov.b64 rc, {%5, %6};\n\t"
        "fma.rn.f32x2 rc, ra, rb, rc;\n\t"
        "mov.b64 {%0, %1}, rc;\n\t"
        "}"
        : "=f"(d.x), "=f"(d.y)
        : "f"(a), "f"(b.x), "f"(b.y), "f"(c.x), "f"(c.y));
    return d;
}

__device__ __forceinline__ float4 ffma4s(float a, float4 b, float4 c) {
    float2 lo = ffma2s(a, make_float2(b.x, b.y), make_float2(c.x, c.y));
    float2 hi = ffma2s(a, make_float2(b.z, b.w), make_float2(c.z, c.w));
    return make_float4(lo.x, lo.y, hi.x, hi.y);
}

// ---------------------------------------------------------------------------
// Kernel 0: fuse o_w into v_w per head (writes k-major transposed).
// ---------------------------------------------------------------------------
__global__ void k_fuse(const float* __restrict__ o_w, const float* __restrict__ v_w,
                       const float* __restrict__ v_b) {
    const int h = blockIdx.x;
    const int o = threadIdx.x;  // 64 threads
    __shared__ float svw[CC * CC];
    __shared__ float svb[CC];
    for (int i = o; i < CC * CC; i += blockDim.x) svw[i] = v_w[i];
    if (o < CC) svb[o] = v_b[o];
    __syncthreads();

    float wrow[CC];
#pragma unroll
    for (int m = 0; m < CC; m++) wrow[m] = o_w[o * (CC * HH) + h * CC + m];

    for (int k = 0; k < CC; k++) {
        float s = 0.f;
#pragma unroll
        for (int m = 0; m < CC; m++) s += wrow[m] * svw[m * CC + k];
        g_wf_t[h][k][o] = s;
    }
    float s = 0.f;
#pragma unroll
    for (int m = 0; m < CC; m++) s += wrow[m] * svb[m];
    g_wf_t[h][KA - 1][o] = s;
}

// ---------------------------------------------------------------------------
// Kernel 1: partial scores.
// smem: sW [2][64][64]=8192 (m-major: [p][m][c]) | sB 128 | sX [2][64][52]=6656
//       sQ [2][64][52]=6656  -> total 21632 floats = 86528 B
// ---------------------------------------------------------------------------
__global__ void __launch_bounds__(512, 1) k_scores(
    const float* __restrict__ x_q, const float* __restrict__ x_kv,
    const float* __restrict__ q_w, const float* __restrict__ q_b,
    const float* __restrict__ k_w, const float* __restrict__ k_b) {
    extern __shared__ float sm[];
    float* sW = sm;           // [p][m][c]  (c contiguous -> vector weight loads)
    float* sB = sm + 8192;
    float* sX = sm + 8320;    // [p][64][52] padded (pad cols zero)
    float* sQ = sm + 14976;   // [p][64][52] padded

    const int tid = threadIdx.x;
    const int ch  = blockIdx.x;
    const int n   = blockIdx.y;
    const int t0  = ch * TPC;

    // transposed weight load: sW[p][m*64 + c] = w[c*64 + m]
    for (int i = tid; i < CC * CC; i += 512) {
        const int c = i >> 6, m = i & 63;
        sW[m * 64 + c]        = q_w[i];
        sW[4096 + m * 64 + c] = k_w[i];
    }
    if (tid < CC) { sB[tid] = q_b[tid]; sB[64 + tid] = k_b[tid]; }

    // scores slot decomposition: 8h x 13(u-quad) x 13(v-quad) = 1352 slots
    int sh[3], su[3], sv[3];
    bool val[3];
    float4 acc[3][4];
#pragma unroll
    for (int it = 0; it < 3; it++) {
        const int s = tid + it * 512;
        val[it] = (s < 1352);
        const int ss = val[it] ? s : 0;
        sh[it] = ss / 169;
        const int r = ss % 169;
        su[it] = (r / 13) * 4;
        sv[it] = (r % 13) * 4;
#pragma unroll
        for (int i = 0; i < 4; i++) acc[it][i] = make_float4(0.f, 0.f, 0.f, 0.f);
    }

    // projection mapping: 208 active threads, 8 c-rows x 4 u-cols each
    const bool pact = tid < 208;
    const int  pp   = tid / 104;
    const int  prem = tid % 104;
    const int  pc0  = (prem / 13) * 8;
    const int  pu0  = (prem % 13) * 4;

    __syncthreads();

    for (int tt = 0; tt < TPC; tt++) {
        const int t = t0 + tt;
        for (int i = tid; i < 2 * 64 * 52; i += 512) {
            const int p = i / 3328;
            const int rr = i - p * 3328;
            const int m = rr / 52, u = rr - m * 52;
            float v = 0.f;
            if (u < VV) {
                const float* src = p ? x_kv : x_q;
                v = src[((long)(n * CC + m) * TT + t) * VV + u];
            }
            sX[i] = v;
        }
        __syncthreads();

        if (pact) {
            float4 a[8];
            const float* bb = sB + pp * 64 + pc0;
#pragma unroll
            for (int j = 0; j < 8; j++) { const float b = bb[j]; a[j] = make_float4(b, b, b, b); }
            const float* wb = sW + pp * 4096 + pc0;
            const float* xb = sX + pp * 3328 + pu0;
#pragma unroll
            for (int m = 0; m < 64; m++) {
                const float4 w0 = *(const float4*)(wb + m * 64);
                const float4 w1 = *(const float4*)(wb + m * 64 + 4);
                const float4 x4 = *(const float4*)(xb + m * 52);
                a[0] = ffma4s(w0.x, x4, a[0]);
                a[1] = ffma4s(w0.y, x4, a[1]);
                a[2] = ffma4s(w0.z, x4, a[2]);
                a[3] = ffma4s(w0.w, x4, a[3]);
                a[4] = ffma4s(w1.x, x4, a[4]);
                a[5] = ffma4s(w1.y, x4, a[5]);
                a[6] = ffma4s(w1.z, x4, a[6]);
                a[7] = ffma4s(w1.w, x4, a[7]);
            }
            float* qb = sQ + pp * 3328 + pc0 * 52 + pu0;
#pragma unroll
            for (int j = 0; j < 8; j++) *(float4*)(qb + j * 52) = a[j];
        }
        __syncthreads();

#pragma unroll
        for (int it = 0; it < 3; it++) {
            if (val[it]) {
                const float* qb = sQ + (sh[it] * 8) * 52 + su[it];
                const float* kb = sQ + 3328 + (sh[it] * 8) * 52 + sv[it];
#pragma unroll
                for (int cl = 0; cl < 8; cl++) {
                    const float4 q4 = *(const float4*)(qb + cl * 52);
                    const float4 kv = *(const float4*)(kb + cl * 52);
                    acc[it][0] = ffma4s(q4.x, kv, acc[it][0]);
                    acc[it][1] = ffma4s(q4.y, kv, acc[it][1]);
                    acc[it][2] = ffma4s(q4.z, kv, acc[it][2]);
                    acc[it][3] = ffma4s(q4.w, kv, acc[it][3]);
                }
            }
        }
        __syncthreads();
    }

#pragma unroll
    for (int it = 0; it < 3; it++) {
        if (val[it]) {
#pragma unroll
            for (int i = 0; i < 4; i++) {
                const int u = su[it] + i;
                if (u < VV) {
                    float* dst = &g_spart[ch][n][sh[it]][u][sv[it]];
                    const float4 a4 = acc[it][i];
                    dst[0] = a4.x; dst[1] = a4.y;
                    if (sv[it] + 2 < VV) { dst[2] = a4.z; dst[3] = a4.w; }
                }
            }
        }
    }
}

// ---------------------------------------------------------------------------
// Kernel 1b: reduce partials, attn = tanh(S/(hc*T))*alpha[h] + global_attn
// ---------------------------------------------------------------------------
__global__ void k_attn(const float* __restrict__ alphas, const float* __restrict__ gattn) {
    const int idx = blockIdx.x * blockDim.x + threadIdx.x;
    if (idx >= NN * HH * VV * VV) return;
    const int n  = idx / (HH * VV * VV);
    const int r  = idx - n * (HH * VV * VV);
    const int h  = r / (VV * VV);
    const int uv = r - h * (VV * VV);
    float s = 0.f;
#pragma unroll
    for (int c2 = 0; c2 < TCH; c2++)
        s += ((const float*)g_spart)[((long)(c2 * NN + n) * HH + h) * (VV * VV) + uv];
    const float a = tanhf(s * (1.0f / (HCC * TT))) * alphas[h] + gattn[uv];
    ((float*)g_attn)[idx] = a;
}

// ---------------------------------------------------------------------------
// Kernel 2: fused v-proj + values + o-proj.
// smem: sX [65][112]=7280 | sW [65][64]=4160 | sU [64][112]=7168 | sA [56][56]=3136
// total 21744 floats = 86976 B  (2 blocks/SM)
// col index pc -> (tl = pc/56, u = pc%56); u >= 50 cols are exact zeros.
// ---------------------------------------------------------------------------
__global__ void __launch_bounds__(256, 2) k_out(const float* __restrict__ x_kv,
                                                const float* __restrict__ o_b,
                                                float* __restrict__ out) {
    extern __shared__ float sm[];
    float* sX = sm;            // [65][112]
    float* sW = sm + 7280;     // [65][64] k-major
    float* sU = sm + 11440;    // [64][112]
    float* sA = sm + 18608;    // [56][56] (rows/cols >= 50 zero)

    const int tid = threadIdx.x;
    const int n   = blockIdx.y;
    const int t0  = blockIdx.x * TB;

    // load X_aug (zeros in pad cols; ones-row = 64)
    for (int i = tid; i < KA * 2 * UP; i += 256) {
        const int row = i / (2 * UP), pc = i - row * (2 * UP);
        const int tl = pc / UP, u = pc - tl * UP;
        float v = 0.f;
        if (u < VV)
            v = (row == 64) ? 1.f
                            : x_kv[((long)(n * CC + row) * TT + t0 + tl) * VV + u];
        sX[i] = v;
    }

    const bool act = tid < 224;
    // stage A mapping: 8 o-rows x 4 cols
    const int aog = tid / 28;            // 0..7
    const int ac0 = (tid % 28) * 4;      // col base
    // stage B mapping: 4 o-rows x 8 v x 1 tl
    const int bo0 = (tid / 14) * 4;      // 0..60
    const int br  = tid % 14;
    const int btl = br / 7;
    const int bv0 = (br % 7) * 8;

    float4 accB[4][2];
#pragma unroll
    for (int j = 0; j < 4; j++) {
        accB[j][0] = make_float4(0.f, 0.f, 0.f, 0.f);
        accB[j][1] = make_float4(0.f, 0.f, 0.f, 0.f);
    }

    for (int h = 0; h < HH; h++) {
        __syncthreads();  // prev stage B done with sU/sA (covers X load at h=0)
        for (int i = tid; i < KA * CC; i += 256)
            sW[i] = ((const float*)g_wf_t)[h * (KA * CC) + i];
        for (int i = tid; i < UP * UP; i += 256) {
            const int row = i / UP, col = i - row * UP;
            sA[i] = (row < VV && col < VV) ? g_attn[n][h][row][col] : 0.f;
        }
        __syncthreads();

        // stage A: U = W_fh @ X_aug
        if (act) {
            float4 a[8];
#pragma unroll
            for (int j = 0; j < 8; j++) a[j] = make_float4(0.f, 0.f, 0.f, 0.f);
            const float* wb = sW + aog * 8;
            const float* xb = sX + ac0;
#pragma unroll
            for (int k = 0; k < KA; k++) {
                const float4 w0 = *(const float4*)(wb + k * 64);
                const float4 w1 = *(const float4*)(wb + k * 64 + 4);
                const float4 x4 = *(const float4*)(xb + k * (2 * UP));
                a[0] = ffma4s(w0.x, x4, a[0]);
                a[1] = ffma4s(w0.y, x4, a[1]);
                a[2] = ffma4s(w0.z, x4, a[2]);
                a[3] = ffma4s(w0.w, x4, a[3]);
                a[4] = ffma4s(w1.x, x4, a[4]);
                a[5] = ffma4s(w1.y, x4, a[5]);
                a[6] = ffma4s(w1.z, x4, a[6]);
                a[7] = ffma4s(w1.w, x4, a[7]);
            }
            float* ub = sU + (aog * 8) * (2 * UP) + ac0;
#pragma unroll
            for (int j = 0; j < 8; j++) *(float4*)(ub + j * (2 * UP)) = a[j];
        }
        __syncthreads();

        // stage B: acc += U_h @ A_h (4o x 8v per thread, full u)
        if (act) {
            const float* ub = sU + bo0 * (2 * UP) + btl * UP;
            const float* ab = sA + bv0;
            for (int uu = 0; uu < UP; uu += 4) {
                float4 u4[4];
#pragma unroll
                for (int j = 0; j < 4; j++) u4[j] = *(const float4*)(ub + j * (2 * UP) + uu);
#pragma unroll
                for (int i = 0; i < 4; i++) {
                    const float4 av0 = *(const float4*)(ab + (uu + i) * UP);
                    const float4 av1 = *(const float4*)(ab + (uu + i) * UP + 4);
#pragma unroll
                    for (int j = 0; j < 4; j++) {
                        const float us = (i == 0) ? u4[j].x : (i == 1) ? u4[j].y
                                        : (i == 2) ? u4[j].z : u4[j].w;
                        accB[j][0] = ffma4s(us, av0, accB[j][0]);
                        accB[j][1] = ffma4s(us, av1, accB[j][1]);
                    }
                }
            }
        }
    }

    // epilogue
    if (act) {
#pragma unroll
        for (int j = 0; j < 4; j++) {
            const int o = bo0 + j;
            const float ob = o_b[o];
            const long base = ((long)(n * CC + o) * TT + t0 + btl) * VV + bv0;
            float vals[8];
            vals[0] = accB[j][0].x; vals[1] = accB[j][0].y;
            vals[2] = accB[j][0].z; vals[3] = accB[j][0].w;
            vals[4] = accB[j][1].x; vals[5] = accB[j][1].y;
            vals[6] = accB[j][1].z; vals[7] = accB[j][1].w;
#pragma unroll
            for (int e = 0; e < 8; e++)
                if (bv0 + e < VV) out[base + e] = vals[e] + ob;
        }
    }
}

// ---------------------------------------------------------------------------
extern "C" void kernel_launch(void* const* d_in, const int* in_sizes, int n_in,
                              void* d_out, int out_size) {
    const float* x_q    = (const float*)d_in[0];
    const float* x_kv   = (const float*)d_in[1];
    const float* q_w    = (const float*)d_in[2];
    const float* q_b    = (const float*)d_in[3];
    const float* k_w    = (const float*)d_in[4];
    const float* k_b    = (const float*)d_in[5];
    const float* v_w    = (const float*)d_in[6];
    const float* v_b    = (const float*)d_in[7];
    const float* o_w    = (const float*)d_in[8];
    const float* o_b    = (const float*)d_in[9];
    const float* alphas = (const float*)d_in[10];
    const float* gattn  = (const float*)d_in[11];
    float* out = (float*)d_out;

    const int smem1 = 21632 * sizeof(float);  // 86528 B
    const int smem2 = 21744 * sizeof(float);  // 86976 B
    cudaFuncSetAttribute(k_scores, cudaFuncAttributeMaxDynamicSharedMemorySize, smem1);
    cudaFuncSetAttribute(k_out,    cudaFuncAttributeMaxDynamicSharedMemorySize, smem2);

    k_fuse<<<HH, 64>>>(o_w, v_w, v_b);
    k_scores<<<dim3(TCH, NN), 512, smem1>>>(x_q, x_kv, q_w, q_b, k_w, k_b);
    k_attn<<<(NN * HH * VV * VV + 255) / 256, 256>>>(alphas, gattn);
    k_out<<<dim3(TT / TB, NN), 256, smem2>>>(x_kv, o_b, out);
}

// round 7
// speedup vs baseline: 1.1034x; 1.1034x over previous
#include <cuda_runtime.h>

// Problem constants
#define NN  32
#define CC  64
#define TT  256
#define VV  50
#define HH  8
#define HCC 8
#define KA  65            // augmented K (64 channels + bias row)
#define TCH 8             // t-chunks for scores kernel
#define TPC (TT / TCH)    // 32 t per scores block
#define TB  2             // t per block in fused output kernel
#define UP  56            // padded u/v extent in k_out

// Scratch (static device memory — no allocations allowed)
__device__ float g_wf_t[HH][KA][CC];               // fused weights, k-major: [h][k][o]
__device__ float g_spart[TCH][NN][HH][VV][VV];     // partial scores
__device__ float g_attn[NN][HH][VV][VV];           // tanh(scores)*alpha + global_attn

// Packed fp32x2 FMA with scalar multiplier broadcast (Blackwell FFMA2)
__device__ __forceinline__ float2 ffma2s(float a, float2 b, float2 c) {
    float2 d;
    asm("{\n\t"
        ".reg .b64 ra, rb, rc;\n\t"
        "mov.b64 ra, {%2, %2};\n\t"
        "mov.b64 rb, {%3, %4};\n\t"
        "mov.b64 rc, {%5, %6};\n\t"
        "fma.rn.f32x2 rc, ra, rb, rc;\n\t"
        "mov.b64 {%0, %1}, rc;\n\t"
        "}"
        : "=f"(d.x), "=f"(d.y)
        : "f"(a), "f"(b.x), "f"(b.y), "f"(c.x), "f"(c.y));
    return d;
}

__device__ __forceinline__ float4 ffma4s(float a, float4 b, float4 c) {
    float2 lo = ffma2s(a, make_float2(b.x, b.y), make_float2(c.x, c.y));
    float2 hi = ffma2s(a, make_float2(b.z, b.w), make_float2(c.z, c.w));
    return make_float4(lo.x, lo.y, hi.x, hi.y);
}

// ---------------------------------------------------------------------------
// Kernel 0: fuse o_w into v_w per head (writes k-major transposed).
// ---------------------------------------------------------------------------
__global__ void k_fuse(const float* __restrict__ o_w, const float* __restrict__ v_w,
                       const float* __restrict__ v_b) {
    const int h = blockIdx.x;
    const int o = threadIdx.x;  // 64 threads
    __shared__ float svw[CC * CC];
    __shared__ float svb[CC];
    for (int i = o; i < CC * CC; i += blockDim.x) svw[i] = v_w[i];
    if (o < CC) svb[o] = v_b[o];
    __syncthreads();

    float wrow[CC];
#pragma unroll
    for (int m = 0; m < CC; m++) wrow[m] = o_w[o * (CC * HH) + h * CC + m];

    for (int k = 0; k < CC; k++) {
        float s = 0.f;
#pragma unroll
        for (int m = 0; m < CC; m++) s += wrow[m] * svw[m * CC + k];
        g_wf_t[h][k][o] = s;
    }
    float s = 0.f;
#pragma unroll
    for (int m = 0; m < CC; m++) s += wrow[m] * svb[m];
    g_wf_t[h][KA - 1][o] = s;
}

// ---------------------------------------------------------------------------
// Kernel 1: partial scores (R3 version — known-good 1984us composite).
// smem: sW [2][64][65]=8320 | sB 128 | sX [2][64][50]=6400 | sQ [2][64][52]=6656
// ---------------------------------------------------------------------------
__global__ void __launch_bounds__(512, 1) k_scores(
    const float* __restrict__ x_q, const float* __restrict__ x_kv,
    const float* __restrict__ q_w, const float* __restrict__ q_b,
    const float* __restrict__ k_w, const float* __restrict__ k_b) {
    extern __shared__ float sm[];
    float* sW = sm;           // [p][64][65] padded rows
    float* sB = sm + 8320;
    float* sX = sm + 8448;    // [p][64][50]
    float* sQ = sm + 14848;   // [p][64][52] padded

    const int tid = threadIdx.x;
    const int ch  = blockIdx.x;
    const int n   = blockIdx.y;
    const int t0  = ch * TPC;

    for (int i = tid; i < CC * CC; i += 512) {
        const int c = i >> 6, m = i & 63;
        sW[c * 65 + m]        = q_w[i];
        sW[4160 + c * 65 + m] = k_w[i];
    }
    if (tid < CC) { sB[tid] = q_b[tid]; sB[64 + tid] = k_b[tid]; }
    for (int i = tid; i < 2 * 64 * 2; i += 512) {
        const int p = i >> 7, r = (i >> 1) & 63, c = i & 1;
        sQ[p * 3328 + r * 52 + 50 + c] = 0.f;
    }

    int sh[3], su[3], sv[3];
    bool val[3];
    float4 acc[3][4];
#pragma unroll
    for (int it = 0; it < 3; it++) {
        const int s = tid + it * 512;
        val[it] = (s < 1352);
        const int ss = val[it] ? s : 0;
        sh[it] = ss / 169;
        const int r = ss % 169;
        su[it] = (r / 13) * 4;
        sv[it] = (r % 13) * 4;
#pragma unroll
        for (int i = 0; i < 4; i++) acc[it][i] = make_float4(0.f, 0.f, 0.f, 0.f);
    }

    const bool pact = tid < 400;
    const int  pp   = tid / 200;
    const int  prem = tid % 200;
    const int  pog  = (prem / 25) * 8;
    const int  pcp  = (prem % 25) * 2;

    __syncthreads();

    for (int tt = 0; tt < TPC; tt++) {
        const int t = t0 + tt;
        for (int i = tid; i < 6400; i += 512) {
            const int half = i / 3200;
            const int r = i - half * 3200;
            const int c = r / 50, v = r - c * 50;
            const float* src = half ? x_kv : x_q;
            sX[i] = src[((long)(n * CC + c) * TT + t) * VV + v];
        }
        __syncthreads();

        if (pact) {
            float2 a[8];
            const float* wb = sW + pp * 4160 + pog * 65;
            const float* bb = sB + pp * 64 + pog;
#pragma unroll
            for (int j = 0; j < 8; j++) { const float b = bb[j]; a[j] = make_float2(b, b); }
            const float* xb = sX + pp * 3200 + pcp;
#pragma unroll
            for (int m = 0; m < 64; m++) {
                const float2 xv = *(const float2*)(xb + m * 50);
#pragma unroll
                for (int j = 0; j < 8; j++) a[j] = ffma2s(wb[j * 65 + m], xv, a[j]);
            }
            float* qb = sQ + pp * 3328 + pog * 52 + pcp;
#pragma unroll
            for (int j = 0; j < 8; j++) *(float2*)(qb + j * 52) = a[j];
        }
        __syncthreads();

#pragma unroll
        for (int it = 0; it < 3; it++) {
            if (val[it]) {
                const float* qb = sQ + (sh[it] * 8) * 52 + su[it];
                const float* kb = sQ + 3328 + (sh[it] * 8) * 52 + sv[it];
#pragma unroll
                for (int cl = 0; cl < 8; cl++) {
                    const float4 kv = *(const float4*)(kb + cl * 52);
#pragma unroll
                    for (int i = 0; i < 4; i++)
                        acc[it][i] = ffma4s(qb[cl * 52 + i], kv, acc[it][i]);
                }
            }
        }
        __syncthreads();
    }

#pragma unroll
    for (int it = 0; it < 3; it++) {
        if (val[it]) {
#pragma unroll
            for (int i = 0; i < 4; i++) {
                const int u = su[it] + i;
                if (u < VV) {
                    float* dst = &g_spart[ch][n][sh[it]][u][sv[it]];
                    const float4 a4 = acc[it][i];
                    dst[0] = a4.x; dst[1] = a4.y;
                    if (sv[it] + 2 < VV) { dst[2] = a4.z; dst[3] = a4.w; }
                }
            }
        }
    }
}

// ---------------------------------------------------------------------------
// Kernel 1b: reduce partials, attn = tanh(S/(hc*T))*alpha[h] + global_attn
// ---------------------------------------------------------------------------
__global__ void k_attn(const float* __restrict__ alphas, const float* __restrict__ gattn) {
    const int idx = blockIdx.x * blockDim.x + threadIdx.x;
    if (idx >= NN * HH * VV * VV) return;
    const int n  = idx / (HH * VV * VV);
    const int r  = idx - n * (HH * VV * VV);
    const int h  = r / (VV * VV);
    const int uv = r - h * (VV * VV);
    float s = 0.f;
#pragma unroll
    for (int c2 = 0; c2 < TCH; c2++)
        s += ((const float*)g_spart)[((long)(c2 * NN + n) * HH + h) * (VV * VV) + uv];
    const float a = tanhf(s * (1.0f / (HCC * TT))) * alphas[h] + gattn[uv];
    ((float*)g_attn)[idx] = a;
}

// ---------------------------------------------------------------------------
// Kernel 2: fused v-proj + values + o-proj, warp-uniform o-group mapping.
// smem: sX [65][112]=7280 | sW [65][64]=4160 (k-major) | sU [64][112]=7168
//       sA [56][56]=3136   total 21744 floats = 86976 B  (2 blocks/SM)
// Mapping (224 active): grp = tid/28 (o-group, WARP-UNIFORM), r28 = tid%28.
//   stage A: cols ac0 = r28*4                      (8 o-rows x 4 cols)
//   stage B: btl = r28/14, bv0 = (r28%14)*4        (8 o-rows x 4 v x 1 t)
// u4 loads in stage B are warp broadcasts; av loads are dense consecutive.
// ---------------------------------------------------------------------------
__global__ void __launch_bounds__(256, 2) k_out(const float* __restrict__ x_kv,
                                                const float* __restrict__ o_b,
                                                float* __restrict__ out) {
    extern __shared__ float sm[];
    float* sX = sm;            // [65][112]
    float* sW = sm + 7280;     // [65][64] k-major
    float* sU = sm + 11440;    // [64][112]
    float* sA = sm + 18608;    // [56][56] (rows/cols >= 50 zero)

    const int tid = threadIdx.x;
    const int n   = blockIdx.y;
    const int t0  = blockIdx.x * TB;

    // load X_aug (zeros in pad cols; ones-row = 64)
    for (int i = tid; i < KA * 2 * UP; i += 256) {
        const int row = i / (2 * UP), pc = i - row * (2 * UP);
        const int tl = pc / UP, u = pc - tl * UP;
        float v = 0.f;
        if (u < VV)
            v = (row == 64) ? 1.f
                            : x_kv[((long)(n * CC + row) * TT + t0 + tl) * VV + u];
        sX[i] = v;
    }

    const bool act = tid < 224;
    const int  grp = tid / 28;           // o-group 0..7, warp-uniform
    const int  r28 = tid % 28;
    const int  ac0 = r28 * 4;            // stage A col base (0..108)
    const int  btl = r28 / 14;           // stage B t within pair
    const int  bv0 = (r28 % 14) * 4;     // stage B v base (0..52)

    float4 accB[8];
#pragma unroll
    for (int j = 0; j < 8; j++) accB[j] = make_float4(0.f, 0.f, 0.f, 0.f);

    for (int h = 0; h < HH; h++) {
        __syncthreads();  // prev stage B done with sU/sA/sW (covers X load at h=0)
        for (int i = tid; i < KA * CC; i += 256)
            sW[i] = ((const float*)g_wf_t)[h * (KA * CC) + i];
        for (int i = tid; i < UP * UP; i += 256) {
            const int row = i / UP, col = i - row * UP;
            sA[i] = (row < VV && col < VV) ? g_attn[n][h][row][col] : 0.f;
        }
        __syncthreads();

        // stage A: U = W_fh @ X_aug.  8 o-rows x 4 cols per thread.
        // weight loads: 2 broadcast LDS.128/k; x loads: dense 4 wf/k.
        if (act) {
            float4 a[8];
#pragma unroll
            for (int j = 0; j < 8; j++) a[j] = make_float4(0.f, 0.f, 0.f, 0.f);
            const float* wb = sW + grp * 8;
            const float* xb = sX + ac0;
#pragma unroll
            for (int k = 0; k < KA; k++) {
                const float4 w0 = *(const float4*)(wb + k * 64);
                const float4 w1 = *(const float4*)(wb + k * 64 + 4);
                const float4 x4 = *(const float4*)(xb + k * (2 * UP));
                a[0] = ffma4s(w0.x, x4, a[0]);
                a[1] = ffma4s(w0.y, x4, a[1]);
                a[2] = ffma4s(w0.z, x4, a[2]);
                a[3] = ffma4s(w0.w, x4, a[3]);
                a[4] = ffma4s(w1.x, x4, a[4]);
                a[5] = ffma4s(w1.y, x4, a[5]);
                a[6] = ffma4s(w1.z, x4, a[6]);
                a[7] = ffma4s(w1.w, x4, a[7]);
            }
            float* ub = sU + (grp * 8) * (2 * UP) + ac0;
#pragma unroll
            for (int j = 0; j < 8; j++) *(float4*)(ub + j * (2 * UP)) = a[j];
        }
        __syncthreads();

        // stage B: acc += U_h @ A_h.  8 o-rows x 4 v x 1 t per thread.
        if (act) {
            const float* ub = sU + (grp * 8) * (2 * UP) + btl * UP;
            const float* ab = sA + bv0;
#pragma unroll 2
            for (int uu = 0; uu < UP; uu += 4) {
                float4 u4[8];
#pragma unroll
                for (int j = 0; j < 8; j++)             // warp broadcasts
                    u4[j] = *(const float4*)(ub + j * (2 * UP) + uu);
#pragma unroll
                for (int i = 0; i < 4; i++) {
                    const float4 av = *(const float4*)(ab + (uu + i) * UP);
#pragma unroll
                    for (int j = 0; j < 8; j++) {
                        const float us = (i == 0) ? u4[j].x : (i == 1) ? u4[j].y
                                        : (i == 2) ? u4[j].z : u4[j].w;
                        accB[j] = ffma4s(us, av, accB[j]);
                    }
                }
            }
        }
    }

    // epilogue
    if (act) {
#pragma unroll
        for (int j = 0; j < 8; j++) {
            const int o = grp * 8 + j;
            const float ob = o_b[o];
            const long base = ((long)(n * CC + o) * TT + t0 + btl) * VV + bv0;
            const float4 r = accB[j];
            if (bv0 < VV) {
                out[base]     = r.x + ob;
                out[base + 1] = r.y + ob;
                if (bv0 + 2 < VV) {
                    out[base + 2] = r.z + ob;
                    out[base + 3] = r.w + ob;
                }
            }
        }
    }
}

// ---------------------------------------------------------------------------
extern "C" void kernel_launch(void* const* d_in, const int* in_sizes, int n_in,
                              void* d_out, int out_size) {
    const float* x_q    = (const float*)d_in[0];
    const float* x_kv   = (const float*)d_in[1];
    const float* q_w    = (const float*)d_in[2];
    const float* q_b    = (const float*)d_in[3];
    const float* k_w    = (const float*)d_in[4];
    const float* k_b    = (const float*)d_in[5];
    const float* v_w    = (const float*)d_in[6];
    const float* v_b    = (const float*)d_in[7];
    const float* o_w    = (const float*)d_in[8];
    const float* o_b    = (const float*)d_in[9];
    const float* alphas = (const float*)d_in[10];
    const float* gattn  = (const float*)d_in[11];
    float* out = (float*)d_out;

    const int smem1 = 21504 * sizeof(float);  // 86016 B
    const int smem2 = 21744 * sizeof(float);  // 86976 B
    cudaFuncSetAttribute(k_scores, cudaFuncAttributeMaxDynamicSharedMemorySize, smem1);
    cudaFuncSetAttribute(k_out,    cudaFuncAttributeMaxDynamicSharedMemorySize, smem2);

    k_fuse<<<HH, 64>>>(o_w, v_w, v_b);
    k_scores<<<dim3(TCH, NN), 512, smem1>>>(x_q, x_kv, q_w, q_b, k_w, k_b);
    k_attn<<<(NN * HH * VV * VV + 255) / 256, 256>>>(alphas, gattn);
    k_out<<<dim3(TT / TB, NN), 256, smem2>>>(x_kv, o_b, out);
}

// round 8
// speedup vs baseline: 1.1051x; 1.0015x over previous
#include <cuda_runtime.h>

// Problem constants
#define NN  32
#define CC  64
#define TT  256
#define VV  50
#define HH  8
#define HCC 8
#define KA  65            // augmented K (64 channels + bias row)
#define TCH 8             // t-chunks for scores kernel
#define TPC (TT / TCH)    // 32 t per scores block
#define TB  2             // t per block in fused output kernel
#define UP  56            // padded u/v extent in k_out

// Scratch (static device memory — no allocations allowed)
__device__ float g_wf_t[HH][KA][CC];               // fused weights, k-major: [h][k][o]
__device__ float g_spart[TCH][NN][HH][VV][VV];     // partial scores
__device__ float g_attn[NN][HH][VV][VV];           // tanh(scores)*alpha + global_attn

// Packed fp32x2 FMA with scalar multiplier broadcast (Blackwell FFMA2)
__device__ __forceinline__ float2 ffma2s(float a, float2 b, float2 c) {
    float2 d;
    asm("{\n\t"
        ".reg .b64 ra, rb, rc;\n\t"
        "mov.b64 ra, {%2, %2};\n\t"
        "mov.b64 rb, {%3, %4};\n\t"
        "mov.b64 rc, {%5, %6};\n\t"
        "fma.rn.f32x2 rc, ra, rb, rc;\n\t"
        "mov.b64 {%0, %1}, rc;\n\t"
        "}"
        : "=f"(d.x), "=f"(d.y)
        : "f"(a), "f"(b.x), "f"(b.y), "f"(c.x), "f"(c.y));
    return d;
}

__device__ __forceinline__ float4 ffma4s(float a, float4 b, float4 c) {
    float2 lo = ffma2s(a, make_float2(b.x, b.y), make_float2(c.x, c.y));
    float2 hi = ffma2s(a, make_float2(b.z, b.w), make_float2(c.z, c.w));
    return make_float4(lo.x, lo.y, hi.x, hi.y);
}

// ---------------------------------------------------------------------------
// Kernel 0: fuse o_w into v_w per head (writes k-major transposed).
// ---------------------------------------------------------------------------
__global__ void k_fuse(const float* __restrict__ o_w, const float* __restrict__ v_w,
                       const float* __restrict__ v_b) {
    const int h = blockIdx.x;
    const int o = threadIdx.x;  // 64 threads
    __shared__ float svw[CC * CC];
    __shared__ float svb[CC];
    for (int i = o; i < CC * CC; i += blockDim.x) svw[i] = v_w[i];
    if (o < CC) svb[o] = v_b[o];
    __syncthreads();

    float wrow[CC];
#pragma unroll
    for (int m = 0; m < CC; m++) wrow[m] = o_w[o * (CC * HH) + h * CC + m];

    for (int k = 0; k < CC; k++) {
        float s = 0.f;
#pragma unroll
        for (int m = 0; m < CC; m++) s += wrow[m] * svw[m * CC + k];
        g_wf_t[h][k][o] = s;
    }
    float s = 0.f;
#pragma unroll
    for (int m = 0; m < CC; m++) s += wrow[m] * svb[m];
    g_wf_t[h][KA - 1][o] = s;
}

// ---------------------------------------------------------------------------
// Kernel 1: partial scores (R3 version — known-good 1984us composite).
// smem: sW [2][64][65]=8320 | sB 128 | sX [2][64][50]=6400 | sQ [2][64][52]=6656
// ---------------------------------------------------------------------------
__global__ void __launch_bounds__(512, 1) k_scores(
    const float* __restrict__ x_q, const float* __restrict__ x_kv,
    const float* __restrict__ q_w, const float* __restrict__ q_b,
    const float* __restrict__ k_w, const float* __restrict__ k_b) {
    extern __shared__ float sm[];
    float* sW = sm;           // [p][64][65] padded rows
    float* sB = sm + 8320;
    float* sX = sm + 8448;    // [p][64][50]
    float* sQ = sm + 14848;   // [p][64][52] padded

    const int tid = threadIdx.x;
    const int ch  = blockIdx.x;
    const int n   = blockIdx.y;
    const int t0  = ch * TPC;

    for (int i = tid; i < CC * CC; i += 512) {
        const int c = i >> 6, m = i & 63;
        sW[c * 65 + m]        = q_w[i];
        sW[4160 + c * 65 + m] = k_w[i];
    }
    if (tid < CC) { sB[tid] = q_b[tid]; sB[64 + tid] = k_b[tid]; }
    for (int i = tid; i < 2 * 64 * 2; i += 512) {
        const int p = i >> 7, r = (i >> 1) & 63, c = i & 1;
        sQ[p * 3328 + r * 52 + 50 + c] = 0.f;
    }

    int sh[3], su[3], sv[3];
    bool val[3];
    float4 acc[3][4];
#pragma unroll
    for (int it = 0; it < 3; it++) {
        const int s = tid + it * 512;
        val[it] = (s < 1352);
        const int ss = val[it] ? s : 0;
        sh[it] = ss / 169;
        const int r = ss % 169;
        su[it] = (r / 13) * 4;
        sv[it] = (r % 13) * 4;
#pragma unroll
        for (int i = 0; i < 4; i++) acc[it][i] = make_float4(0.f, 0.f, 0.f, 0.f);
    }

    const bool pact = tid < 400;
    const int  pp   = tid / 200;
    const int  prem = tid % 200;
    const int  pog  = (prem / 25) * 8;
    const int  pcp  = (prem % 25) * 2;

    __syncthreads();

    for (int tt = 0; tt < TPC; tt++) {
        const int t = t0 + tt;
        for (int i = tid; i < 6400; i += 512) {
            const int half = i / 3200;
            const int r = i - half * 3200;
            const int c = r / 50, v = r - c * 50;
            const float* src = half ? x_kv : x_q;
            sX[i] = src[((long)(n * CC + c) * TT + t) * VV + v];
        }
        __syncthreads();

        if (pact) {
            float2 a[8];
            const float* wb = sW + pp * 4160 + pog * 65;
            const float* bb = sB + pp * 64 + pog;
#pragma unroll
            for (int j = 0; j < 8; j++) { const float b = bb[j]; a[j] = make_float2(b, b); }
            const float* xb = sX + pp * 3200 + pcp;
#pragma unroll
            for (int m = 0; m < 64; m++) {
                const float2 xv = *(const float2*)(xb + m * 50);
#pragma unroll
                for (int j = 0; j < 8; j++) a[j] = ffma2s(wb[j * 65 + m], xv, a[j]);
            }
            float* qb = sQ + pp * 3328 + pog * 52 + pcp;
#pragma unroll
            for (int j = 0; j < 8; j++) *(float2*)(qb + j * 52) = a[j];
        }
        __syncthreads();

#pragma unroll
        for (int it = 0; it < 3; it++) {
            if (val[it]) {
                const float* qb = sQ + (sh[it] * 8) * 52 + su[it];
                const float* kb = sQ + 3328 + (sh[it] * 8) * 52 + sv[it];
#pragma unroll
                for (int cl = 0; cl < 8; cl++) {
                    const float4 kv = *(const float4*)(kb + cl * 52);
#pragma unroll
                    for (int i = 0; i < 4; i++)
                        acc[it][i] = ffma4s(qb[cl * 52 + i], kv, acc[it][i]);
                }
            }
        }
        __syncthreads();
    }

#pragma unroll
    for (int it = 0; it < 3; it++) {
        if (val[it]) {
#pragma unroll
            for (int i = 0; i < 4; i++) {
                const int u = su[it] + i;
                if (u < VV) {
                    float* dst = &g_spart[ch][n][sh[it]][u][sv[it]];
                    const float4 a4 = acc[it][i];
                    dst[0] = a4.x; dst[1] = a4.y;
                    if (sv[it] + 2 < VV) { dst[2] = a4.z; dst[3] = a4.w; }
                }
            }
        }
    }
}

// ---------------------------------------------------------------------------
// Kernel 1b: reduce partials, attn = tanh(S/(hc*T))*alpha[h] + global_attn
// ---------------------------------------------------------------------------
__global__ void k_attn(const float* __restrict__ alphas, const float* __restrict__ gattn) {
    const int idx = blockIdx.x * blockDim.x + threadIdx.x;
    if (idx >= NN * HH * VV * VV) return;
    const int n  = idx / (HH * VV * VV);
    const int r  = idx - n * (HH * VV * VV);
    const int h  = r / (VV * VV);
    const int uv = r - h * (VV * VV);
    float s = 0.f;
#pragma unroll
    for (int c2 = 0; c2 < TCH; c2++)
        s += ((const float*)g_spart)[((long)(c2 * NN + n) * HH + h) * (VV * VV) + uv];
    const float a = tanhf(s * (1.0f / (HCC * TT))) * alphas[h] + gattn[uv];
    ((float*)g_attn)[idx] = a;
}

// ---------------------------------------------------------------------------
// Kernel 2: fused v-proj + values + o-proj, warp-uniform o-group mapping.
// smem: sX [65][112]=7280 | sW [65][64]=4160 (k-major) | sU [64][112]=7168
//       sA [56][56]=3136   total 21744 floats = 86976 B  (2 blocks/SM)
// Mapping (224 active): grp = tid/28 (o-group, WARP-UNIFORM), r28 = tid%28.
//   stage A: cols ac0 = r28*4                      (8 o-rows x 4 cols)
//   stage B: btl = r28/14, bv0 = (r28%14)*4        (8 o-rows x 4 v x 1 t)
// u4 loads in stage B are warp broadcasts; av loads are dense consecutive.
// ---------------------------------------------------------------------------
__global__ void __launch_bounds__(256, 2) k_out(const float* __restrict__ x_kv,
                                                const float* __restrict__ o_b,
                                                float* __restrict__ out) {
    extern __shared__ float sm[];
    float* sX = sm;            // [65][112]
    float* sW = sm + 7280;     // [65][64] k-major
    float* sU = sm + 11440;    // [64][112]
    float* sA = sm + 18608;    // [56][56] (rows/cols >= 50 zero)

    const int tid = threadIdx.x;
    const int n   = blockIdx.y;
    const int t0  = blockIdx.x * TB;

    // load X_aug (zeros in pad cols; ones-row = 64)
    for (int i = tid; i < KA * 2 * UP; i += 256) {
        const int row = i / (2 * UP), pc = i - row * (2 * UP);
        const int tl = pc / UP, u = pc - tl * UP;
        float v = 0.f;
        if (u < VV)
            v = (row == 64) ? 1.f
                            : x_kv[((long)(n * CC + row) * TT + t0 + tl) * VV + u];
        sX[i] = v;
    }

    const bool act = tid < 224;
    const int  grp = tid / 28;           // o-group 0..7, warp-uniform
    const int  r28 = tid % 28;
    const int  ac0 = r28 * 4;            // stage A col base (0..108)
    const int  btl = r28 / 14;           // stage B t within pair
    const int  bv0 = (r28 % 14) * 4;     // stage B v base (0..52)

    float4 accB[8];
#pragma unroll
    for (int j = 0; j < 8; j++) accB[j] = make_float4(0.f, 0.f, 0.f, 0.f);

    for (int h = 0; h < HH; h++) {
        __syncthreads();  // prev stage B done with sU/sA/sW (covers X load at h=0)
        for (int i = tid; i < KA * CC; i += 256)
            sW[i] = ((const float*)g_wf_t)[h * (KA * CC) + i];
        for (int i = tid; i < UP * UP; i += 256) {
            const int row = i / UP, col = i - row * UP;
            sA[i] = (row < VV && col < VV) ? g_attn[n][h][row][col] : 0.f;
        }
        __syncthreads();

        // stage A: U = W_fh @ X_aug.  8 o-rows x 4 cols per thread.
        // weight loads: 2 broadcast LDS.128/k; x loads: dense 4 wf/k.
        if (act) {
            float4 a[8];
#pragma unroll
            for (int j = 0; j < 8; j++) a[j] = make_float4(0.f, 0.f, 0.f, 0.f);
            const float* wb = sW + grp * 8;
            const float* xb = sX + ac0;
#pragma unroll
            for (int k = 0; k < KA; k++) {
                const float4 w0 = *(const float4*)(wb + k * 64);
                const float4 w1 = *(const float4*)(wb + k * 64 + 4);
                const float4 x4 = *(const float4*)(xb + k * (2 * UP));
                a[0] = ffma4s(w0.x, x4, a[0]);
                a[1] = ffma4s(w0.y, x4, a[1]);
                a[2] = ffma4s(w0.z, x4, a[2]);
                a[3] = ffma4s(w0.w, x4, a[3]);
                a[4] = ffma4s(w1.x, x4, a[4]);
                a[5] = ffma4s(w1.y, x4, a[5]);
                a[6] = ffma4s(w1.z, x4, a[6]);
                a[7] = ffma4s(w1.w, x4, a[7]);
            }
            float* ub = sU + (grp * 8) * (2 * UP) + ac0;
#pragma unroll
            for (int j = 0; j < 8; j++) *(float4*)(ub + j * (2 * UP)) = a[j];
        }
        __syncthreads();

        // stage B: acc += U_h @ A_h.  8 o-rows x 4 v x 1 t per thread.
        if (act) {
            const float* ub = sU + (grp * 8) * (2 * UP) + btl * UP;
            const float* ab = sA + bv0;
#pragma unroll 2
            for (int uu = 0; uu < UP; uu += 4) {
                float4 u4[8];
#pragma unroll
                for (int j = 0; j < 8; j++)             // warp broadcasts
                    u4[j] = *(const float4*)(ub + j * (2 * UP) + uu);
#pragma unroll
                for (int i = 0; i < 4; i++) {
                    const float4 av = *(const float4*)(ab + (uu + i) * UP);
#pragma unroll
                    for (int j = 0; j < 8; j++) {
                        const float us = (i == 0) ? u4[j].x : (i == 1) ? u4[j].y
                                        : (i == 2) ? u4[j].z : u4[j].w;
                        accB[j] = ffma4s(us, av, accB[j]);
                    }
                }
            }
        }
    }

    // epilogue
    if (act) {
#pragma unroll
        for (int j = 0; j < 8; j++) {
            const int o = grp * 8 + j;
            const float ob = o_b[o];
            const long base = ((long)(n * CC + o) * TT + t0 + btl) * VV + bv0;
            const float4 r = accB[j];
            if (bv0 < VV) {
                out[base]     = r.x + ob;
                out[base + 1] = r.y + ob;
                if (bv0 + 2 < VV) {
                    out[base + 2] = r.z + ob;
                    out[base + 3] = r.w + ob;
                }
            }
        }
    }
}

// ---------------------------------------------------------------------------
extern "C" void kernel_launch(void* const* d_in, const int* in_sizes, int n_in,
                              void* d_out, int out_size) {
    const float* x_q    = (const float*)d_in[0];
    const float* x_kv   = (const float*)d_in[1];
    const float* q_w    = (const float*)d_in[2];
    const float* q_b    = (const float*)d_in[3];
    const float* k_w    = (const float*)d_in[4];
    const float* k_b    = (const float*)d_in[5];
    const float* v_w    = (const float*)d_in[6];
    const float* v_b    = (const float*)d_in[7];
    const float* o_w    = (const float*)d_in[8];
    const float* o_b    = (const float*)d_in[9];
    const float* alphas = (const float*)d_in[10];
    const float* gattn  = (const float*)d_in[11];
    float* out = (float*)d_out;

    const int smem1 = 21504 * sizeof(float);  // 86016 B
    const int smem2 = 21744 * sizeof(float);  // 86976 B
    cudaFuncSetAttribute(k_scores, cudaFuncAttributeMaxDynamicSharedMemorySize, smem1);
    cudaFuncSetAttribute(k_out,    cudaFuncAttributeMaxDynamicSharedMemorySize, smem2);

    k_fuse<<<HH, 64>>>(o_w, v_w, v_b);
    k_scores<<<dim3(TCH, NN), 512, smem1>>>(x_q, x_kv, q_w, q_b, k_w, k_b);
    k_attn<<<(NN * HH * VV * VV + 255) / 256, 256>>>(alphas, gattn);
    k_out<<<dim3(TT / TB, NN), 256, smem2>>>(x_kv, o_b, out);
}

// round 9
// speedup vs baseline: 1.1053x; 1.0002x over previous
#include <cuda_runtime.h>

// Problem constants
#define NN  32
#define CC  64
#define TT  256
#define VV  50
#define HH  8
#define HCC 8
#define KA  65            // augmented K (64 channels + bias row)
#define TCH 8             // t-chunks for scores kernel
#define TPC (TT / TCH)    // 32 t per scores block
#define TB  2             // t per block in fused output kernel
#define UP  56            // padded u/v extent in k_out

// Scratch (static device memory — no allocations allowed)
__device__ float g_wf_t[HH][KA][CC];               // fused weights, k-major: [h][k][o]
__device__ float g_spart[TCH][NN][HH][VV][VV];     // partial scores
__device__ float g_attn[NN][HH][VV][VV];           // tanh(scores)*alpha + global_attn

// Packed fp32x2 FMA with scalar multiplier broadcast (Blackwell FFMA2)
__device__ __forceinline__ float2 ffma2s(float a, float2 b, float2 c) {
    float2 d;
    asm("{\n\t"
        ".reg .b64 ra, rb, rc;\n\t"
        "mov.b64 ra, {%2, %2};\n\t"
        "mov.b64 rb, {%3, %4};\n\t"
        "mov.b64 rc, {%5, %6};\n\t"
        "fma.rn.f32x2 rc, ra, rb, rc;\n\t"
        "mov.b64 {%0, %1}, rc;\n\t"
        "}"
        : "=f"(d.x), "=f"(d.y)
        : "f"(a), "f"(b.x), "f"(b.y), "f"(c.x), "f"(c.y));
    return d;
}

__device__ __forceinline__ float4 ffma4s(float a, float4 b, float4 c) {
    float2 lo = ffma2s(a, make_float2(b.x, b.y), make_float2(c.x, c.y));
    float2 hi = ffma2s(a, make_float2(b.z, b.w), make_float2(c.z, c.w));
    return make_float4(lo.x, lo.y, hi.x, hi.y);
}

// ---------------------------------------------------------------------------
// Kernel 0: fuse o_w into v_w per head (writes k-major transposed).
// ---------------------------------------------------------------------------
__global__ void k_fuse(const float* __restrict__ o_w, const float* __restrict__ v_w,
                       const float* __restrict__ v_b) {
    const int h = blockIdx.x;
    const int o = threadIdx.x;  // 64 threads
    __shared__ float svw[CC * CC];
    __shared__ float svb[CC];
    for (int i = o; i < CC * CC; i += blockDim.x) svw[i] = v_w[i];
    if (o < CC) svb[o] = v_b[o];
    __syncthreads();

    float wrow[CC];
#pragma unroll
    for (int m = 0; m < CC; m++) wrow[m] = o_w[o * (CC * HH) + h * CC + m];

    for (int k = 0; k < CC; k++) {
        float s = 0.f;
#pragma unroll
        for (int m = 0; m < CC; m++) s += wrow[m] * svw[m * CC + k];
        g_wf_t[h][k][o] = s;
    }
    float s = 0.f;
#pragma unroll
    for (int m = 0; m < CC; m++) s += wrow[m] * svb[m];
    g_wf_t[h][KA - 1][o] = s;
}

// ---------------------------------------------------------------------------
// Kernel 1: partial scores (R3 version — known-good 1984us composite).
// smem: sW [2][64][65]=8320 | sB 128 | sX [2][64][50]=6400 | sQ [2][64][52]=6656
// ---------------------------------------------------------------------------
__global__ void __launch_bounds__(512, 1) k_scores(
    const float* __restrict__ x_q, const float* __restrict__ x_kv,
    const float* __restrict__ q_w, const float* __restrict__ q_b,
    const float* __restrict__ k_w, const float* __restrict__ k_b) {
    extern __shared__ float sm[];
    float* sW = sm;           // [p][64][65] padded rows
    float* sB = sm + 8320;
    float* sX = sm + 8448;    // [p][64][50]
    float* sQ = sm + 14848;   // [p][64][52] padded

    const int tid = threadIdx.x;
    const int ch  = blockIdx.x;
    const int n   = blockIdx.y;
    const int t0  = ch * TPC;

    for (int i = tid; i < CC * CC; i += 512) {
        const int c = i >> 6, m = i & 63;
        sW[c * 65 + m]        = q_w[i];
        sW[4160 + c * 65 + m] = k_w[i];
    }
    if (tid < CC) { sB[tid] = q_b[tid]; sB[64 + tid] = k_b[tid]; }
    for (int i = tid; i < 2 * 64 * 2; i += 512) {
        const int p = i >> 7, r = (i >> 1) & 63, c = i & 1;
        sQ[p * 3328 + r * 52 + 50 + c] = 0.f;
    }

    int sh[3], su[3], sv[3];
    bool val[3];
    float4 acc[3][4];
#pragma unroll
    for (int it = 0; it < 3; it++) {
        const int s = tid + it * 512;
        val[it] = (s < 1352);
        const int ss = val[it] ? s : 0;
        sh[it] = ss / 169;
        const int r = ss % 169;
        su[it] = (r / 13) * 4;
        sv[it] = (r % 13) * 4;
#pragma unroll
        for (int i = 0; i < 4; i++) acc[it][i] = make_float4(0.f, 0.f, 0.f, 0.f);
    }

    const bool pact = tid < 400;
    const int  pp   = tid / 200;
    const int  prem = tid % 200;
    const int  pog  = (prem / 25) * 8;
    const int  pcp  = (prem % 25) * 2;

    __syncthreads();

    for (int tt = 0; tt < TPC; tt++) {
        const int t = t0 + tt;
        for (int i = tid; i < 6400; i += 512) {
            const int half = i / 3200;
            const int r = i - half * 3200;
            const int c = r / 50, v = r - c * 50;
            const float* src = half ? x_kv : x_q;
            sX[i] = src[((long)(n * CC + c) * TT + t) * VV + v];
        }
        __syncthreads();

        if (pact) {
            float2 a[8];
            const float* wb = sW + pp * 4160 + pog * 65;
            const float* bb = sB + pp * 64 + pog;
#pragma unroll
            for (int j = 0; j < 8; j++) { const float b = bb[j]; a[j] = make_float2(b, b); }
            const float* xb = sX + pp * 3200 + pcp;
#pragma unroll
            for (int m = 0; m < 64; m++) {
                const float2 xv = *(const float2*)(xb + m * 50);
#pragma unroll
                for (int j = 0; j < 8; j++) a[j] = ffma2s(wb[j * 65 + m], xv, a[j]);
            }
            float* qb = sQ + pp * 3328 + pog * 52 + pcp;
#pragma unroll
            for (int j = 0; j < 8; j++) *(float2*)(qb + j * 52) = a[j];
        }
        __syncthreads();

#pragma unroll
        for (int it = 0; it < 3; it++) {
            if (val[it]) {
                const float* qb = sQ + (sh[it] * 8) * 52 + su[it];
                const float* kb = sQ + 3328 + (sh[it] * 8) * 52 + sv[it];
#pragma unroll
                for (int cl = 0; cl < 8; cl++) {
                    const float4 kv = *(const float4*)(kb + cl * 52);
#pragma unroll
                    for (int i = 0; i < 4; i++)
                        acc[it][i] = ffma4s(qb[cl * 52 + i], kv, acc[it][i]);
                }
            }
        }
        __syncthreads();
    }

#pragma unroll
    for (int it = 0; it < 3; it++) {
        if (val[it]) {
#pragma unroll
            for (int i = 0; i < 4; i++) {
                const int u = su[it] + i;
                if (u < VV) {
                    float* dst = &g_spart[ch][n][sh[it]][u][sv[it]];
                    const float4 a4 = acc[it][i];
                    dst[0] = a4.x; dst[1] = a4.y;
                    if (sv[it] + 2 < VV) { dst[2] = a4.z; dst[3] = a4.w; }
                }
            }
        }
    }
}

// ---------------------------------------------------------------------------
// Kernel 1b: reduce partials, attn = tanh(S/(hc*T))*alpha[h] + global_attn
// ---------------------------------------------------------------------------
__global__ void k_attn(const float* __restrict__ alphas, const float* __restrict__ gattn) {
    const int idx = blockIdx.x * blockDim.x + threadIdx.x;
    if (idx >= NN * HH * VV * VV) return;
    const int n  = idx / (HH * VV * VV);
    const int r  = idx - n * (HH * VV * VV);
    const int h  = r / (VV * VV);
    const int uv = r - h * (VV * VV);
    float s = 0.f;
#pragma unroll
    for (int c2 = 0; c2 < TCH; c2++)
        s += ((const float*)g_spart)[((long)(c2 * NN + n) * HH + h) * (VV * VV) + uv];
    const float a = tanhf(s * (1.0f / (HCC * TT))) * alphas[h] + gattn[uv];
    ((float*)g_attn)[idx] = a;
}

// ---------------------------------------------------------------------------
// Kernel 2: fused v-proj + values + o-proj, warp-uniform o-group mapping.
// smem: sX [65][112]=7280 | sW [65][64]=4160 (k-major) | sU [64][112]=7168
//       sA [56][56]=3136   total 21744 floats = 86976 B  (2 blocks/SM)
// Mapping (224 active): grp = tid/28 (o-group, WARP-UNIFORM), r28 = tid%28.
//   stage A: cols ac0 = r28*4                      (8 o-rows x 4 cols)
//   stage B: btl = r28/14, bv0 = (r28%14)*4        (8 o-rows x 4 v x 1 t)
// u4 loads in stage B are warp broadcasts; av loads are dense consecutive.
// ---------------------------------------------------------------------------
__global__ void __launch_bounds__(256, 2) k_out(const float* __restrict__ x_kv,
                                                const float* __restrict__ o_b,
                                                float* __restrict__ out) {
    extern __shared__ float sm[];
    float* sX = sm;            // [65][112]
    float* sW = sm + 7280;     // [65][64] k-major
    float* sU = sm + 11440;    // [64][112]
    float* sA = sm + 18608;    // [56][56] (rows/cols >= 50 zero)

    const int tid = threadIdx.x;
    const int n   = blockIdx.y;
    const int t0  = blockIdx.x * TB;

    // load X_aug (zeros in pad cols; ones-row = 64)
    for (int i = tid; i < KA * 2 * UP; i += 256) {
        const int row = i / (2 * UP), pc = i - row * (2 * UP);
        const int tl = pc / UP, u = pc - tl * UP;
        float v = 0.f;
        if (u < VV)
            v = (row == 64) ? 1.f
                            : x_kv[((long)(n * CC + row) * TT + t0 + tl) * VV + u];
        sX[i] = v;
    }

    const bool act = tid < 224;
    const int  grp = tid / 28;           // o-group 0..7, warp-uniform
    const int  r28 = tid % 28;
    const int  ac0 = r28 * 4;            // stage A col base (0..108)
    const int  btl = r28 / 14;           // stage B t within pair
    const int  bv0 = (r28 % 14) * 4;     // stage B v base (0..52)

    float4 accB[8];
#pragma unroll
    for (int j = 0; j < 8; j++) accB[j] = make_float4(0.f, 0.f, 0.f, 0.f);

    for (int h = 0; h < HH; h++) {
        __syncthreads();  // prev stage B done with sU/sA/sW (covers X load at h=0)
        for (int i = tid; i < KA * CC; i += 256)
            sW[i] = ((const float*)g_wf_t)[h * (KA * CC) + i];
        for (int i = tid; i < UP * UP; i += 256) {
            const int row = i / UP, col = i - row * UP;
            sA[i] = (row < VV && col < VV) ? g_attn[n][h][row][col] : 0.f;
        }
        __syncthreads();

        // stage A: U = W_fh @ X_aug.  8 o-rows x 4 cols per thread.
        // weight loads: 2 broadcast LDS.128/k; x loads: dense 4 wf/k.
        if (act) {
            float4 a[8];
#pragma unroll
            for (int j = 0; j < 8; j++) a[j] = make_float4(0.f, 0.f, 0.f, 0.f);
            const float* wb = sW + grp * 8;
            const float* xb = sX + ac0;
#pragma unroll
            for (int k = 0; k < KA; k++) {
                const float4 w0 = *(const float4*)(wb + k * 64);
                const float4 w1 = *(const float4*)(wb + k * 64 + 4);
                const float4 x4 = *(const float4*)(xb + k * (2 * UP));
                a[0] = ffma4s(w0.x, x4, a[0]);
                a[1] = ffma4s(w0.y, x4, a[1]);
                a[2] = ffma4s(w0.z, x4, a[2]);
                a[3] = ffma4s(w0.w, x4, a[3]);
                a[4] = ffma4s(w1.x, x4, a[4]);
                a[5] = ffma4s(w1.y, x4, a[5]);
                a[6] = ffma4s(w1.z, x4, a[6]);
                a[7] = ffma4s(w1.w, x4, a[7]);
            }
            float* ub = sU + (grp * 8) * (2 * UP) + ac0;
#pragma unroll
            for (int j = 0; j < 8; j++) *(float4*)(ub + j * (2 * UP)) = a[j];
        }
        __syncthreads();

        // stage B: acc += U_h @ A_h.  8 o-rows x 4 v x 1 t per thread.
        if (act) {
            const float* ub = sU + (grp * 8) * (2 * UP) + btl * UP;
            const float* ab = sA + bv0;
#pragma unroll 2
            for (int uu = 0; uu < UP; uu += 4) {
                float4 u4[8];
#pragma unroll
                for (int j = 0; j < 8; j++)             // warp broadcasts
                    u4[j] = *(const float4*)(ub + j * (2 * UP) + uu);
#pragma unroll
                for (int i = 0; i < 4; i++) {
                    const float4 av = *(const float4*)(ab + (uu + i) * UP);
#pragma unroll
                    for (int j = 0; j < 8; j++) {
                        const float us = (i == 0) ? u4[j].x : (i == 1) ? u4[j].y
                                        : (i == 2) ? u4[j].z : u4[j].w;
                        accB[j] = ffma4s(us, av, accB[j]);
                    }
                }
            }
        }
    }

    // epilogue
    if (act) {
#pragma unroll
        for (int j = 0; j < 8; j++) {
            const int o = grp * 8 + j;
            const float ob = o_b[o];
            const long base = ((long)(n * CC + o) * TT + t0 + btl) * VV + bv0;
            const float4 r = accB[j];
            if (bv0 < VV) {
                out[base]     = r.x + ob;
                out[base + 1] = r.y + ob;
                if (bv0 + 2 < VV) {
                    out[base + 2] = r.z + ob;
                    out[base + 3] = r.w + ob;
                }
            }
        }
    }
}

// ---------------------------------------------------------------------------
extern "C" void kernel_launch(void* const* d_in, const int* in_sizes, int n_in,
                              void* d_out, int out_size) {
    const float* x_q    = (const float*)d_in[0];
    const float* x_kv   = (const float*)d_in[1];
    const float* q_w    = (const float*)d_in[2];
    const float* q_b    = (const float*)d_in[3];
    const float* k_w    = (const float*)d_in[4];
    const float* k_b    = (const float*)d_in[5];
    const float* v_w    = (const float*)d_in[6];
    const float* v_b    = (const float*)d_in[7];
    const float* o_w    = (const float*)d_in[8];
    const float* o_b    = (const float*)d_in[9];
    const float* alphas = (const float*)d_in[10];
    const float* gattn  = (const float*)d_in[11];
    float* out = (float*)d_out;

    const int smem1 = 21504 * sizeof(float);  // 86016 B
    const int smem2 = 21744 * sizeof(float);  // 86976 B
    cudaFuncSetAttribute(k_scores, cudaFuncAttributeMaxDynamicSharedMemorySize, smem1);
    cudaFuncSetAttribute(k_out,    cudaFuncAttributeMaxDynamicSharedMemorySize, smem2);

    k_fuse<<<HH, 64>>>(o_w, v_w, v_b);
    k_scores<<<dim3(TCH, NN), 512, smem1>>>(x_q, x_kv, q_w, q_b, k_w, k_b);
    k_attn<<<(NN * HH * VV * VV + 255) / 256, 256>>>(alphas, gattn);
    k_out<<<dim3(TT / TB, NN), 256, smem2>>>(x_kv, o_b, out);
}